// round 17
// baseline (speedup 1.0000x reference)
#include <cuda_runtime.h>
#include <math.h>

// ---------------------------------------------------------------------------
// SimpleVQ: B=32, H=1, L=4096, D=64, S=512
// Outputs (f32): quantized[B*H*L*D] | z[B*H*L] | l_commit | errs2[B*H*L]
// R13 (roofline-verified exact FFMA2 scan, 243.8us) + fused final reduction.
// ---------------------------------------------------------------------------

typedef unsigned long long ull;

#define NVEC   131072
#define DIMD   64
#define NCODE  512
#define NPAIR  256
#define ZOFF   8388608
#define LOFF   8519680
#define EOFF   8519681
#define NBLK   256
#define SMEM_BYTES (131072 + 2048 + 1024)

__device__ float4 g_cbq[NPAIR * 32];
__device__ float  g_cn[NCODE];
__device__ float  g_part[NBLK];
__device__ int    g_ticket;

// ---- packed f32x2 helpers --------------------------------------------------
__device__ __forceinline__ ull pack2(float x, float y) {
    ull r; asm("mov.b64 %0, {%1, %2};" : "=l"(r) : "f"(x), "f"(y)); return r;
}
__device__ __forceinline__ void unpack2(ull v, float &x, float &y) {
    asm("mov.b64 {%0, %1}, %2;" : "=f"(x), "=f"(y) : "l"(v));
}
__device__ __forceinline__ void ffma2(ull &acc, ull a, ull b) {
    asm("fma.rn.f32x2 %0, %1, %2, %0;" : "+l"(acc) : "l"(a), "l"(b));
}

// ---------------------------------------------------------------------------
// Init: 512 blocks x 64 threads; double trig; writes pair-quad layout.
// Also resets the ticket (deterministic across graph replays).
// ---------------------------------------------------------------------------
__global__ void vq_init() {
    __shared__ float red[64];
    const int s = blockIdx.x;
    const int d = threadIdx.x;
    const int j = d & 31;
    if (s == 0 && d == 0) g_ticket = 0;

    double expn = -((double)(2 * j) / 64.0);
    float  il   = (float)pow(100000.0, expn);
    float  pre  = __fmul_rn((float)s, il);
    float  e    = (d < 32) ? (float)sin((double)pre) : (float)cos((double)pre);

    red[d] = __fmul_rn(e, e);
    __syncthreads();
    for (int o = 32; o > 0; o >>= 1) {
        if (d < o) red[d] = __fadd_rn(red[d], red[d + o]);
        __syncthreads();
    }
    float m = __fadd_rn(__fmul_rn(red[0], (1.0f / 64.0f)), 1e-6f);
    __syncthreads();
    float r = (float)(1.0 / sqrt((double)m));
    float c = __fmul_rn(__fmul_rn(e, r), 0.35355339059327373f);

    float* cb = (float*)g_cbq;
    const int p = s >> 1, col = s & 1;
    cb[(p * 32 + (d >> 1)) * 4 + (d & 1) * 2 + col] = c;

    red[d] = __fmul_rn(c, c);
    __syncthreads();
    for (int o = 32; o > 0; o >>= 1) {
        if (d < o) red[d] = __fadd_rn(red[d], red[d + o]);
        __syncthreads();
    }
    if (d == 0) g_cn[s] = red[0];
}

// ---------------------------------------------------------------------------
// Main: verbatim R13 scan (roofline-optimal) + last-block l_commit reduction.
// ---------------------------------------------------------------------------
__global__ void __launch_bounds__(256) vq_main(const float* __restrict__ vecs,
                                               const float* __restrict__ mask,
                                               float* __restrict__ out) {
    extern __shared__ unsigned char smem[];
    float4*     scbf = (float4*)smem;
    ulonglong2* scb  = (ulonglong2*)smem;
    float*      scn  = (float*)(smem + 131072);
    float*      sred = scn + NCODE;

    for (int i = threadIdx.x; i < NPAIR * 32; i += 256) scbf[i] = g_cbq[i];
    for (int i = threadIdx.x; i < NCODE; i += 256) scn[i] = g_cn[i];
    __syncthreads();

    const int t  = threadIdx.x;
    const int v0 = blockIdx.x * 512 + t;
    const int v1 = v0 + 256;

    float va[64], vb[64];
    {
        const float4* pa = (const float4*)(vecs + (size_t)v0 * DIMD);
        const float4* pb = (const float4*)(vecs + (size_t)v1 * DIMD);
#pragma unroll
        for (int i = 0; i < 16; i++) {
            float4 x = pa[i];
            va[4*i] = x.x; va[4*i+1] = x.y; va[4*i+2] = x.z; va[4*i+3] = x.w;
            float4 y = pb[i];
            vb[4*i] = y.x; vb[4*i+1] = y.y; vb[4*i+2] = y.z; vb[4*i+3] = y.w;
        }
    }
    float vn0 = 0.f, vn1 = 0.f;
#pragma unroll
    for (int d = 0; d < 64; d++) {
        vn0 = __fadd_rn(vn0, __fmul_rn(va[d], va[d]));
        vn1 = __fadd_rn(vn1, __fmul_rn(vb[d], vb[d]));
    }

    float best0 = 3.4e38f, best1 = 3.4e38f;
    int   bi0 = 0, bi1 = 0;

#pragma unroll 1
    for (int p = 0; p < NPAIR; p += 2) {
        ull a00 = 0ull, a01 = 0ull, a10 = 0ull, a11 = 0ull;
#pragma unroll
        for (int j = 0; j < 32; j++) {
            ulonglong2 c0 = scb[(p + 0) * 32 + j];
            ulonglong2 c1 = scb[(p + 1) * 32 + j];
            ull w0 = pack2(va[2*j],     va[2*j]);
            ull w1 = pack2(va[2*j + 1], va[2*j + 1]);
            ull u0 = pack2(vb[2*j],     vb[2*j]);
            ull u1 = pack2(vb[2*j + 1], vb[2*j + 1]);
            ffma2(a00, w0, c0.x); ffma2(a00, w1, c0.y);
            ffma2(a01, w0, c1.x); ffma2(a01, w1, c1.y);
            ffma2(a10, u0, c0.x); ffma2(a10, u1, c0.y);
            ffma2(a11, u0, c1.x); ffma2(a11, u1, c1.y);
        }
        float q0, q1, q2, q3, r0, r1, r2, r3;
        unpack2(a00, q0, q1); unpack2(a01, q2, q3);
        unpack2(a10, r0, r1); unpack2(a11, r2, r3);
        const int s0 = 2 * p;
        const float cna = scn[s0], cnb = scn[s0 + 1], cnc = scn[s0 + 2], cnd = scn[s0 + 3];
        float d0 = __fadd_rn(fmaf(-2.f, q0, vn0), cna);
        float d1 = __fadd_rn(fmaf(-2.f, q1, vn0), cnb);
        float d2 = __fadd_rn(fmaf(-2.f, q2, vn0), cnc);
        float d3 = __fadd_rn(fmaf(-2.f, q3, vn0), cnd);
        if (d0 < best0) { best0 = d0; bi0 = s0;     }
        if (d1 < best0) { best0 = d1; bi0 = s0 + 1; }
        if (d2 < best0) { best0 = d2; bi0 = s0 + 2; }
        if (d3 < best0) { best0 = d3; bi0 = s0 + 3; }
        float e0 = __fadd_rn(fmaf(-2.f, r0, vn1), cna);
        float e1 = __fadd_rn(fmaf(-2.f, r1, vn1), cnb);
        float e2 = __fadd_rn(fmaf(-2.f, r2, vn1), cnc);
        float e3 = __fadd_rn(fmaf(-2.f, r3, vn1), cnd);
        if (e0 < best1) { best1 = e0; bi1 = s0;     }
        if (e1 < best1) { best1 = e1; bi1 = s0 + 1; }
        if (e2 < best1) { best1 = e2; bi1 = s0 + 2; }
        if (e3 < best1) { best1 = e3; bi1 = s0 + 3; }
    }

    {
        int pw = bi0 >> 1, col = bi0 & 1;
        float2* dst = (float2*)(out + (size_t)v0 * DIMD);
#pragma unroll
        for (int j = 0; j < 32; j++) {
            float4 q = scbf[pw * 32 + j];
            float2 w; w.x = col ? q.y : q.x; w.y = col ? q.w : q.z;
            dst[j] = w;
        }
    }
    {
        int pw = bi1 >> 1, col = bi1 & 1;
        float2* dst = (float2*)(out + (size_t)v1 * DIMD);
#pragma unroll
        for (int j = 0; j < 32; j++) {
            float4 q = scbf[pw * 32 + j];
            float2 w; w.x = col ? q.y : q.x; w.y = col ? q.w : q.z;
            dst[j] = w;
        }
    }

    out[ZOFF + v0] = (float)bi0;
    out[ZOFF + v1] = (float)bi1;
    float er0 = fmaxf(best0, 0.f);
    float er1 = fmaxf(best1, 0.f);
    out[EOFF + v0] = er0;
    out[EOFF + v1] = er1;

    float lsum = __fadd_rn(__fmul_rn(mask[v0], er0), __fmul_rn(mask[v1], er1));
    sred[t] = lsum;
    __syncthreads();
    for (int o = 128; o > 0; o >>= 1) {
        if (t < o) sred[t] = __fadd_rn(sred[t], sred[t + o]);
        __syncthreads();
    }

    // ---- fused final: last block reduces g_part deterministically ----
    __shared__ int slast;
    if (t == 0) {
        g_part[blockIdx.x] = sred[0];
        __threadfence();
        int ticket = atomicAdd(&g_ticket, 1);
        slast = (ticket == NBLK - 1) ? 1 : 0;
        if (slast) g_ticket = 0;          // reset for next graph replay
    }
    __syncthreads();
    if (slast) {
        sred[t] = g_part[t];              // 256 partials, fixed order
        __syncthreads();
        for (int o = 128; o > 0; o >>= 1) {
            if (t < o) sred[t] = __fadd_rn(sred[t], sred[t + o]);
            __syncthreads();
        }
        if (t == 0) out[LOFF] = __fmul_rn(sred[0], (1.0f / 131072.0f));
    }
}

// ---------------------------------------------------------------------------
extern "C" void kernel_launch(void* const* d_in, const int* in_sizes, int n_in,
                              void* d_out, int out_size) {
    (void)in_sizes; (void)n_in; (void)out_size;
    const float* vecs = (const float*)d_in[0];
    const float* mask = (const float*)d_in[1];
    float* out = (float*)d_out;

    cudaFuncSetAttribute(vq_main, cudaFuncAttributeMaxDynamicSharedMemorySize, SMEM_BYTES);

    vq_init<<<NCODE, 64>>>();
    vq_main<<<NBLK, 256, SMEM_BYTES>>>(vecs, mask, out);
}